// round 1
// baseline (speedup 1.0000x reference)
#include <cuda_runtime.h>
#include <math.h>

// ---------------- problem constants ----------------
#define BATCH   2048
#define TT      64
#define BT      (BATCH * TT)      // 131072 rows
#define C       384
#define NH      8
#define HD      48
#define C4      (4 * C)           // 1536
#define QKVN    (3 * C)           // 1152

// ---------------- device scratch (no runtime allocation) ----------------
__device__ float g_h[BT * C];          // h (LN1 out), reused as h2 (LN2 out)
__device__ float g_big[BT * C4];       // qkv [BT,1152] then ffn hidden [BT,1536]
__device__ float g_attn[BT * C];       // attention output, head-concat
__device__ float g_x2[BT * C];         // post-attention residual stream
__device__ float g_wcat[C * QKVN];     // repacked [C, 3*C] qkv weight

// ---------------- weight repack: Wq/Wk/Wv [H,C,D] -> Wcat[c][m*384 + h*48 + d] ----------------
__global__ void prep_w_kernel(const float* __restrict__ Wq,
                              const float* __restrict__ Wk,
                              const float* __restrict__ Wv,
                              float* __restrict__ Wcat) {
    int idx = blockIdx.x * blockDim.x + threadIdx.x;
    if (idx >= 3 * C * C) return;
    int m   = idx / (C * C);
    int rem = idx % (C * C);
    int c   = rem / C;
    int hd  = rem % C;
    int h   = hd / HD;
    int d   = hd % HD;
    const float* W = (m == 0) ? Wq : ((m == 1) ? Wk : Wv);
    Wcat[c * QKVN + m * C + hd] = W[(size_t)h * C * HD + (size_t)c * HD + d];
}

// ---------------- layernorm: one warp per row of C=384 ----------------
__global__ void ln_kernel(const float* __restrict__ x, const float* __restrict__ g,
                          const float* __restrict__ b, float* __restrict__ out) {
    int row  = blockIdx.x * blockDim.y + threadIdx.y;
    int lane = threadIdx.x;
    const float* xr = x + (size_t)row * C;
    float4 v[3];
    float sum = 0.f, sq = 0.f;
#pragma unroll
    for (int i = 0; i < 3; i++) {
        v[i] = *(const float4*)(xr + i * 128 + lane * 4);
        sum += v[i].x + v[i].y + v[i].z + v[i].w;
        sq  += v[i].x * v[i].x + v[i].y * v[i].y + v[i].z * v[i].z + v[i].w * v[i].w;
    }
#pragma unroll
    for (int o = 16; o; o >>= 1) {
        sum += __shfl_xor_sync(0xffffffffu, sum, o);
        sq  += __shfl_xor_sync(0xffffffffu, sq, o);
    }
    float mean = sum * (1.0f / C);
    float var  = sq * (1.0f / C) - mean * mean;
    float rstd = rsqrtf(var + 1e-5f);
    float* orow = out + (size_t)row * C;
#pragma unroll
    for (int i = 0; i < 3; i++) {
        int col = i * 128 + lane * 4;
        float4 gg = *(const float4*)(g + col);
        float4 bb = *(const float4*)(b + col);
        float4 o4;
        o4.x = (v[i].x - mean) * rstd * gg.x + bb.x;
        o4.y = (v[i].y - mean) * rstd * gg.y + bb.y;
        o4.z = (v[i].z - mean) * rstd * gg.z + bb.z;
        o4.w = (v[i].w - mean) * rstd * gg.w + bb.w;
        *(float4*)(orow + col) = o4;
    }
}

// ---------------- tiled fp32 GEMM with packed fma.rn.f32x2 ----------------
// C[M,N] = A[M,K] @ B[K,N]  (+bias) (relu) (+res), all row-major.
// BM=BN=128, BK=8, 256 threads, 8x8 per-thread tile.
__global__ __launch_bounds__(256) void gemm_kernel(
    const float* __restrict__ A, const float* __restrict__ B,
    const float* __restrict__ bias, const float* __restrict__ res,
    float* __restrict__ Cout, int M, int N, int K, int relu)
{
    __shared__ float As[8][128];
    __shared__ float Bs[8][128];
    const int tid = threadIdx.x;
    const int rb  = blockIdx.y * 128;
    const int cb  = blockIdx.x * 128;
    const int tx  = tid & 15;
    const int ty  = tid >> 4;

    const int arow = tid >> 1;         // 0..127
    const int akq  = (tid & 1) * 4;    // 0 or 4
    const int bk   = tid >> 5;         // 0..7
    const int bc   = (tid & 31) * 4;   // 0..124

    const float* Ap = A + (size_t)(rb + arow) * K + akq;
    const float* Bp = B + (size_t)bk * N + cb + bc;

    unsigned long long acc[8][4];
#pragma unroll
    for (int i = 0; i < 8; i++)
#pragma unroll
        for (int j = 0; j < 4; j++) acc[i][j] = 0ull;

    for (int kb = 0; kb < K; kb += 8) {
        float4 av = *(const float4*)(Ap + kb);
        float4 bv = *(const float4*)(Bp + (size_t)kb * N);
        As[akq + 0][arow] = av.x;
        As[akq + 1][arow] = av.y;
        As[akq + 2][arow] = av.z;
        As[akq + 3][arow] = av.w;
        *(float4*)&Bs[bk][bc] = bv;
        __syncthreads();
#pragma unroll
        for (int k = 0; k < 8; k++) {
            float4 a0 = *(const float4*)&As[k][ty * 8];
            float4 a1 = *(const float4*)&As[k][ty * 8 + 4];
            ulonglong2 bb0 = *(const ulonglong2*)&Bs[k][tx * 8];
            ulonglong2 bb1 = *(const ulonglong2*)&Bs[k][tx * 8 + 4];
            unsigned long long b2[4] = { bb0.x, bb0.y, bb1.x, bb1.y };
            float af[8] = { a0.x, a0.y, a0.z, a0.w, a1.x, a1.y, a1.z, a1.w };
#pragma unroll
            for (int i = 0; i < 8; i++) {
                unsigned long long a2;
                unsigned int au = __float_as_uint(af[i]);
                asm("mov.b64 %0, {%1, %1};" : "=l"(a2) : "r"(au));
#pragma unroll
                for (int jp = 0; jp < 4; jp++) {
                    asm("fma.rn.f32x2 %0, %1, %2, %0;"
                        : "+l"(acc[i][jp]) : "l"(a2), "l"(b2[jp]));
                }
            }
        }
        __syncthreads();
    }

    // epilogue
#pragma unroll
    for (int i = 0; i < 8; i++) {
        int r = rb + ty * 8 + i;
        float c8[8];
#pragma unroll
        for (int jp = 0; jp < 4; jp++) {
            unsigned int lo, hi;
            asm("mov.b64 {%0, %1}, %2;" : "=r"(lo), "=r"(hi) : "l"(acc[i][jp]));
            c8[2 * jp]     = __uint_as_float(lo);
            c8[2 * jp + 1] = __uint_as_float(hi);
        }
#pragma unroll
        for (int j = 0; j < 8; j += 4) {
            int cc = cb + tx * 8 + j;
            float4 vv = make_float4(c8[j], c8[j + 1], c8[j + 2], c8[j + 3]);
            if (bias) {
                float4 bb = *(const float4*)(bias + cc);
                vv.x += bb.x; vv.y += bb.y; vv.z += bb.z; vv.w += bb.w;
            }
            if (relu) {
                vv.x = fmaxf(vv.x, 0.f); vv.y = fmaxf(vv.y, 0.f);
                vv.z = fmaxf(vv.z, 0.f); vv.w = fmaxf(vv.w, 0.f);
            }
            if (res) {
                float4 rr = *(const float4*)(res + (size_t)r * N + cc);
                vv.x += rr.x; vv.y += rr.y; vv.z += rr.z; vv.w += rr.w;
            }
            *(float4*)(Cout + (size_t)r * N + cc) = vv;
        }
    }
}

// ---------------- attention: one CTA per (batch, head) ----------------
// qkv layout: row bt, col = m*384 + h*48 + d (m = 0:q, 1:k, 2:v)
__global__ __launch_bounds__(128) void attn_kernel(const float* __restrict__ qkv,
                                                   float* __restrict__ attn_out) {
    extern __shared__ float smem[];
    float* qs = smem;                 // [64][48]
    float* ks = qs + 64 * 48;         // [64][48]
    float* vs = ks + 64 * 48;         // [64][48]
    float* ws = vs + 64 * 48;         // [64][64]

    const int bh = blockIdx.x;
    const int b  = bh >> 3;
    const int h  = bh & 7;
    const int tid = threadIdx.x;
    const size_t base = (size_t)b * TT * QKVN + (size_t)h * HD;

    for (int idx = tid; idx < 64 * 12; idx += 128) {
        int t  = idx / 12;
        int c4 = (idx % 12) * 4;
        const float* p = qkv + base + (size_t)t * QKVN + c4;
        *(float4*)&qs[t * 48 + c4] = *(const float4*)p;
        *(float4*)&ks[t * 48 + c4] = *(const float4*)(p + C);
        *(float4*)&vs[t * 48 + c4] = *(const float4*)(p + 2 * C);
    }
    __syncthreads();

    const float scale = 2.449489742783178f;  // 48 * 384^-0.5

    // scores (lower triangle only)
    for (int idx = tid; idx < 64 * 64; idx += 128) {
        int i = idx >> 6, j = idx & 63;
        if (j > i) continue;
        float sx = 0.f, sy = 0.f, sz = 0.f, sw = 0.f;
#pragma unroll
        for (int d4 = 0; d4 < 12; d4++) {
            float4 qv = *(const float4*)&qs[i * 48 + d4 * 4];
            float4 kv = *(const float4*)&ks[j * 48 + d4 * 4];
            sx += qv.x * kv.x; sy += qv.y * kv.y;
            sz += qv.z * kv.z; sw += qv.w * kv.w;
        }
        ws[i * 64 + j] = (sx + sy + sz + sw) * scale;
    }
    __syncthreads();

    // causal softmax: one thread per row
    if (tid < 64) {
        int i = tid;
        float m = -1e30f;
        for (int j = 0; j <= i; j++) m = fmaxf(m, ws[i * 64 + j]);
        float s = 0.f;
        for (int j = 0; j <= i; j++) {
            float e = expf(ws[i * 64 + j] - m);
            ws[i * 64 + j] = e;
            s += e;
        }
        float inv = 1.f / s;
        for (int j = 0; j <= i; j++) ws[i * 64 + j] *= inv;
    }
    __syncthreads();

    // attn = wei @ v, write head-concat layout [bt, h*48 + d]
    for (int idx = tid; idx < 64 * 12; idx += 128) {
        int i  = idx / 12;
        int d4 = (idx % 12) * 4;
        float ax = 0.f, ay = 0.f, az = 0.f, aw = 0.f;
        for (int j = 0; j <= i; j++) {
            float w = ws[i * 64 + j];
            float4 vv = *(const float4*)&vs[j * 48 + d4];
            ax += w * vv.x; ay += w * vv.y; az += w * vv.z; aw += w * vv.w;
        }
        float* o = attn_out + (size_t)(b * TT + i) * C + h * HD + d4;
        *(float4*)o = make_float4(ax, ay, az, aw);
    }
}

// ---------------- launch ----------------
extern "C" void kernel_launch(void* const* d_in, const int* in_sizes, int n_in,
                              void* d_out, int out_size) {
    const float* x     = (const float*)d_in[0];
    const float* ln1_g = (const float*)d_in[1];
    const float* ln1_b = (const float*)d_in[2];
    const float* ln2_g = (const float*)d_in[3];
    const float* ln2_b = (const float*)d_in[4];
    const float* Wq    = (const float*)d_in[5];
    const float* Wk    = (const float*)d_in[6];
    const float* Wv    = (const float*)d_in[7];
    const float* Wp    = (const float*)d_in[8];
    const float* bp    = (const float*)d_in[9];
    const float* W1    = (const float*)d_in[10];
    const float* b1    = (const float*)d_in[11];
    const float* W2    = (const float*)d_in[12];
    const float* b2    = (const float*)d_in[13];
    float* out = (float*)d_out;

    float *ph, *pbig, *pattn, *px2, *pwcat;
    cudaGetSymbolAddress((void**)&ph, g_h);
    cudaGetSymbolAddress((void**)&pbig, g_big);
    cudaGetSymbolAddress((void**)&pattn, g_attn);
    cudaGetSymbolAddress((void**)&px2, g_x2);
    cudaGetSymbolAddress((void**)&pwcat, g_wcat);

    static int smem_set = 0;
    const int attn_smem = (3 * 64 * 48 + 64 * 64) * (int)sizeof(float);  // 53248 B
    if (!smem_set) {
        cudaFuncSetAttribute(attn_kernel, cudaFuncAttributeMaxDynamicSharedMemorySize, attn_smem);
        smem_set = 1;
    }

    // 1. repack qkv weights into [C, 3C]
    prep_w_kernel<<<(3 * C * C + 255) / 256, 256>>>(Wq, Wk, Wv, pwcat);
    // 2. LN1
    ln_kernel<<<BT / 8, dim3(32, 8)>>>(x, ln1_g, ln1_b, ph);
    // 3. QKV gemm: [BT,384] @ [384,1152]
    gemm_kernel<<<dim3(QKVN / 128, BT / 128), 256>>>(ph, pwcat, nullptr, nullptr, pbig, BT, QKVN, C, 0);
    // 4. attention per (b,h)
    attn_kernel<<<BATCH * NH, 128, attn_smem>>>(pbig, pattn);
    // 5. proj + bias + residual
    gemm_kernel<<<dim3(C / 128, BT / 128), 256>>>(pattn, Wp, bp, x, px2, BT, C, C, 0);
    // 6. LN2
    ln_kernel<<<BT / 8, dim3(32, 8)>>>(px2, ln2_g, ln2_b, ph);
    // 7. FFN1 + bias + relu
    gemm_kernel<<<dim3(C4 / 128, BT / 128), 256>>>(ph, W1, b1, nullptr, pbig, BT, C4, C, 1);
    // 8. FFN2 + bias + residual -> out
    gemm_kernel<<<dim3(C / 128, BT / 128), 256>>>(pbig, W2, b2, px2, out, BT, C, C4, 0);
}

// round 3
// speedup vs baseline: 3.2829x; 3.2829x over previous
#include <cuda_runtime.h>
#include <cuda_bf16.h>
#include <math.h>
#include <stdint.h>

// ---------------- problem constants ----------------
#define BATCH   2048
#define TT      64
#define BT      (BATCH * TT)      // 131072 rows
#define C       384
#define NH      8
#define HD      48
#define C4      1536
#define QKVN    1152

typedef __nv_bfloat16 bf16;

// ---------------- device scratch ----------------
__device__ __align__(256) bf16  g_h_hi[BT * C],   g_h_lo[BT * C];
__device__ __align__(256) float g_qkv[BT * QKVN];
__device__ __align__(256) bf16  g_attn_hi[BT * C], g_attn_lo[BT * C];
__device__ __align__(256) float g_x2[BT * C];
__device__ __align__(256) bf16  g_hid_hi[BT * C4], g_hid_lo[BT * C4];
__device__ __align__(256) bf16  g_wqkv_hi[QKVN * C], g_wqkv_lo[QKVN * C];
__device__ __align__(256) bf16  g_wp_hi[C * C],      g_wp_lo[C * C];
__device__ __align__(256) bf16  g_w1_hi[C4 * C],     g_w1_lo[C4 * C];
__device__ __align__(256) bf16  g_w2_hi[C * C4],     g_w2_lo[C * C4];

// ---------------- PTX helpers (base-arch only: sm_80-level PTX) ----------------
__device__ __forceinline__ uint32_t smem_u32(const void* p) {
    uint32_t a;
    asm("{ .reg .u64 t; cvta.to.shared.u64 t, %1; cvt.u32.u64 %0, t; }" : "=r"(a) : "l"(p));
    return a;
}
__device__ __forceinline__ void cpa16(uint32_t dst, const void* src) {
    asm volatile("cp.async.cg.shared.global [%0], [%1], 16;" :: "r"(dst), "l"(src));
}
#define CP_COMMIT() asm volatile("cp.async.commit_group;" ::: "memory")
#define CP_WAIT(n)  asm volatile("cp.async.wait_group %0;" :: "n"(n) : "memory")

__device__ __forceinline__ void ldsm_x4(uint32_t a, uint32_t* r) {
    asm volatile("ldmatrix.sync.aligned.m8n8.x4.shared.b16 {%0,%1,%2,%3}, [%4];"
                 : "=r"(r[0]), "=r"(r[1]), "=r"(r[2]), "=r"(r[3]) : "r"(a));
}
__device__ __forceinline__ void mma_16816(float* d, const uint32_t* a, const uint32_t* b) {
    asm volatile("mma.sync.aligned.m16n8k16.row.col.f32.bf16.bf16.f32 "
                 "{%0,%1,%2,%3}, {%4,%5,%6,%7}, {%8,%9}, {%0,%1,%2,%3};"
                 : "+f"(d[0]), "+f"(d[1]), "+f"(d[2]), "+f"(d[3])
                 : "r"(a[0]), "r"(a[1]), "r"(a[2]), "r"(a[3]), "r"(b[0]), "r"(b[1]));
}

// ---------------- weight prep ----------------
__device__ __forceinline__ void split_bf16(float v, bf16& h, bf16& l) {
    h = __float2bfloat16(v);
    l = __float2bfloat16(v - __bfloat162float(h));
}

__global__ void prep_qkv_kernel(const float* __restrict__ Wq, const float* __restrict__ Wk,
                                const float* __restrict__ Wv,
                                bf16* __restrict__ hi, bf16* __restrict__ lo) {
    int idx = blockIdx.x * blockDim.x + threadIdx.x;
    if (idx >= QKVN * C) return;
    int n = idx / C, k = idx % C;
    int m = n / C, hd = n % C;
    int h = hd / HD, d = hd % HD;
    const float* W = (m == 0) ? Wq : ((m == 1) ? Wk : Wv);
    split_bf16(W[(size_t)h * C * HD + (size_t)k * HD + d], hi[idx], lo[idx]);
}

__global__ void prep_t_kernel(const float* __restrict__ src, bf16* __restrict__ hi,
                              bf16* __restrict__ lo, int K, int N) {
    int idx = blockIdx.x * blockDim.x + threadIdx.x;
    if (idx >= K * N) return;
    int k = idx / N, n = idx % N;
    split_bf16(src[idx], hi[(size_t)n * K + k], lo[(size_t)n * K + k]);
}

// ---------------- layernorm: one warp per row, outputs hi/lo bf16 ----------------
__global__ void ln_kernel(const float* __restrict__ x, const float* __restrict__ g,
                          const float* __restrict__ b,
                          bf16* __restrict__ out_hi, bf16* __restrict__ out_lo) {
    int row  = blockIdx.x * blockDim.y + threadIdx.y;
    int lane = threadIdx.x;
    const float* xr = x + (size_t)row * C;
    float4 v[3];
    float sum = 0.f, sq = 0.f;
#pragma unroll
    for (int i = 0; i < 3; i++) {
        v[i] = *(const float4*)(xr + i * 128 + lane * 4);
        sum += v[i].x + v[i].y + v[i].z + v[i].w;
        sq  += v[i].x * v[i].x + v[i].y * v[i].y + v[i].z * v[i].z + v[i].w * v[i].w;
    }
#pragma unroll
    for (int o = 16; o; o >>= 1) {
        sum += __shfl_xor_sync(0xffffffffu, sum, o);
        sq  += __shfl_xor_sync(0xffffffffu, sq, o);
    }
    float mean = sum * (1.0f / C);
    float var  = sq * (1.0f / C) - mean * mean;
    float rstd = rsqrtf(var + 1e-5f);
    size_t rbase = (size_t)row * C;
#pragma unroll
    for (int i = 0; i < 3; i++) {
        int col = i * 128 + lane * 4;
        float4 gg = *(const float4*)(g + col);
        float4 bb = *(const float4*)(b + col);
        float o0 = (v[i].x - mean) * rstd * gg.x + bb.x;
        float o1 = (v[i].y - mean) * rstd * gg.y + bb.y;
        float o2 = (v[i].z - mean) * rstd * gg.z + bb.z;
        float o3 = (v[i].w - mean) * rstd * gg.w + bb.w;
        bf16 h0, l0, h1, l1, h2, l2, h3, l3;
        split_bf16(o0, h0, l0); split_bf16(o1, h1, l1);
        split_bf16(o2, h2, l2); split_bf16(o3, h3, l3);
        __nv_bfloat162 hA; hA.x = h0; hA.y = h1;
        __nv_bfloat162 hB; hB.x = h2; hB.y = h3;
        __nv_bfloat162 lA; lA.x = l0; lA.y = l1;
        __nv_bfloat162 lB; lB.x = l2; lB.y = l3;
        *(__nv_bfloat162*)(out_hi + rbase + col)     = hA;
        *(__nv_bfloat162*)(out_hi + rbase + col + 2) = hB;
        *(__nv_bfloat162*)(out_lo + rbase + col)     = lA;
        *(__nv_bfloat162*)(out_lo + rbase + col + 2) = lB;
    }
}

// ---------------- HMMA GEMM: out[M,N] = A[M,K] @ B[N,K]^T, bf16 hi/lo 3-term split ----------------
// MODE 0: store fp32
// MODE 1: +bias +res, store fp32
// MODE 2: +bias, relu, store bf16 hi/lo split
#define BMT 128
#define BNT 128
#define BKT 32
#define STAGE_BYTES 32768
#define GEMM_SMEM   (2 * STAGE_BYTES)
// stage layout: Ahi @0, Alo @8192, Bhi @16384, Blo @24576; row = 64B (32 bf16)
// 16B-chunk swizzle: chunk c of row r stored at c ^ ((r>>1)&3)

__device__ __forceinline__ void tile_load(uint32_t sdst, const bf16* __restrict__ g,
                                          int ld, int tid) {
#pragma unroll
    for (int i = 0; i < 2; i++) {
        int id = tid + i * 256;
        int r = id >> 2, c = id & 3;
        uint32_t dst = sdst + r * 64 + ((c ^ ((r >> 1) & 3)) << 4);
        cpa16(dst, g + (size_t)r * ld + c * 8);
    }
}

__device__ __forceinline__ void compute_stage(uint32_t st, int arow, int a_kc,
                                              int bn, int b_kc,
                                              float (&acc)[4][4][4]) {
#pragma unroll
    for (int ks = 0; ks < 2; ks++) {
        const int akc = ks * 2 + a_kc;
        const int bkc = ks * 2 + b_kc;
        uint32_t a_hi[4][4], a_lo[4][4], b_hi[2][4], b_lo[2][4];
#pragma unroll
        for (int ma = 0; ma < 4; ma++) {
            int r = arow + ma * 16;
            ldsm_x4(st + r * 64 + ((akc ^ ((r >> 1) & 3)) << 4), a_hi[ma]);
        }
#pragma unroll
        for (int p = 0; p < 2; p++) {
            int n = bn + p * 16;
            ldsm_x4(st + 16384 + n * 64 + ((bkc ^ ((n >> 1) & 3)) << 4), b_hi[p]);
        }
#pragma unroll
        for (int ma = 0; ma < 4; ma++)
#pragma unroll
            for (int na = 0; na < 4; na++)
                mma_16816(acc[ma][na], a_hi[ma], &b_hi[na >> 1][(na & 1) * 2]);
#pragma unroll
        for (int p = 0; p < 2; p++) {
            int n = bn + p * 16;
            ldsm_x4(st + 24576 + n * 64 + ((bkc ^ ((n >> 1) & 3)) << 4), b_lo[p]);
        }
#pragma unroll
        for (int ma = 0; ma < 4; ma++)
#pragma unroll
            for (int na = 0; na < 4; na++)
                mma_16816(acc[ma][na], a_hi[ma], &b_lo[na >> 1][(na & 1) * 2]);
#pragma unroll
        for (int ma = 0; ma < 4; ma++) {
            int r = arow + ma * 16;
            ldsm_x4(st + 8192 + r * 64 + ((akc ^ ((r >> 1) & 3)) << 4), a_lo[ma]);
        }
#pragma unroll
        for (int ma = 0; ma < 4; ma++)
#pragma unroll
            for (int na = 0; na < 4; na++)
                mma_16816(acc[ma][na], a_lo[ma], &b_hi[na >> 1][(na & 1) * 2]);
    }
}

template <int MODE>
__global__ __launch_bounds__(256) void mma_gemm(
    const bf16* __restrict__ Ahi, const bf16* __restrict__ Alo,
    const bf16* __restrict__ Bhi, const bf16* __restrict__ Blo,
    const float* __restrict__ bias, const float* __restrict__ res,
    float* __restrict__ outf, bf16* __restrict__ out_hi, bf16* __restrict__ out_lo,
    int N, int K)
{
    extern __shared__ char smem[];
    const uint32_t sb = smem_u32(smem);
    const int tid  = threadIdx.x;
    const int lane = tid & 31;
    const int wid  = tid >> 5;
    const int wm   = wid >> 2;     // 0..1
    const int wn   = wid & 3;      // 0..3
    const int cb   = blockIdx.x * BNT;
    const int rb   = blockIdx.y * BMT;
    const int NC   = K / BKT;

    const bf16* Ahi_t = Ahi + (size_t)rb * K;
    const bf16* Alo_t = Alo + (size_t)rb * K;
    const bf16* Bhi_t = Bhi + (size_t)cb * K;
    const bf16* Blo_t = Blo + (size_t)cb * K;

    float acc[4][4][4];
#pragma unroll
    for (int i = 0; i < 4; i++)
#pragma unroll
        for (int j = 0; j < 4; j++)
#pragma unroll
            for (int q = 0; q < 4; q++) acc[i][j][q] = 0.f;

    // ldmatrix per-lane geometry
    const int arow = wm * 64 + (lane & 15);
    const int a_kc = lane >> 4;              // 0/1
    const int bn   = wn * 32 + ((lane >> 4) << 3) + (lane & 7);
    const int b_kc = (lane >> 3) & 1;

#define ISSUE(cn, s) do {                                              \
        int _kc = (cn) * BKT;                                          \
        uint32_t _st = sb + (s) * STAGE_BYTES;                         \
        tile_load(_st,         Ahi_t + _kc, K, tid);                   \
        tile_load(_st + 8192,  Alo_t + _kc, K, tid);                   \
        tile_load(_st + 16384, Bhi_t + _kc, K, tid);                   \
        tile_load(_st + 24576, Blo_t + _kc, K, tid);                   \
        CP_COMMIT();                                                   \
    } while (0)

    ISSUE(0, 0);
    ISSUE(1, 1);
    CP_WAIT(1);
    __syncthreads();

    for (int c = 0; c < NC; c++) {
        int s = c & 1;
        compute_stage(sb + s * STAGE_BYTES, arow, a_kc, bn, b_kc, acc);
        __syncthreads();
        if (c + 2 < NC) ISSUE(c + 2, s);
        if (c + 1 < NC) {
            if (c + 2 < NC) CP_WAIT(1); else CP_WAIT(0);
            __syncthreads();
        }
    }
#undef ISSUE

    // epilogue
    const int g  = lane >> 2;
    const int tg = lane & 3;
#pragma unroll
    for (int ma = 0; ma < 4; ma++) {
        int r0 = rb + wm * 64 + ma * 16 + g;
#pragma unroll
        for (int na = 0; na < 4; na++) {
            int col = cb + wn * 32 + na * 8 + tg * 2;
            float d0 = acc[ma][na][0], d1 = acc[ma][na][1];
            float d2 = acc[ma][na][2], d3 = acc[ma][na][3];
            if (MODE >= 1) {
                float2 bb = *(const float2*)(bias + col);
                d0 += bb.x; d1 += bb.y; d2 += bb.x; d3 += bb.y;
            }
            if (MODE == 1) {
                float2 ra = *(const float2*)(res + (size_t)r0 * N + col);
                float2 rbv = *(const float2*)(res + (size_t)(r0 + 8) * N + col);
                d0 += ra.x; d1 += ra.y; d2 += rbv.x; d3 += rbv.y;
            }
            if (MODE == 2) {
                d0 = fmaxf(d0, 0.f); d1 = fmaxf(d1, 0.f);
                d2 = fmaxf(d2, 0.f); d3 = fmaxf(d3, 0.f);
                bf16 h0, l0, h1, l1;
                split_bf16(d0, h0, l0); split_bf16(d1, h1, l1);
                __nv_bfloat162 hh; hh.x = h0; hh.y = h1;
                __nv_bfloat162 ll; ll.x = l0; ll.y = l1;
                *(__nv_bfloat162*)(out_hi + (size_t)r0 * N + col) = hh;
                *(__nv_bfloat162*)(out_lo + (size_t)r0 * N + col) = ll;
                split_bf16(d2, h0, l0); split_bf16(d3, h1, l1);
                hh.x = h0; hh.y = h1; ll.x = l0; ll.y = l1;
                *(__nv_bfloat162*)(out_hi + (size_t)(r0 + 8) * N + col) = hh;
                *(__nv_bfloat162*)(out_lo + (size_t)(r0 + 8) * N + col) = ll;
            } else {
                *(float2*)(outf + (size_t)r0 * N + col)       = make_float2(d0, d1);
                *(float2*)(outf + (size_t)(r0 + 8) * N + col) = make_float2(d2, d3);
            }
        }
    }
}

// ---------------- attention: one CTA per (batch, head), fp32, split output ----------------
__global__ __launch_bounds__(128) void attn_kernel(const float* __restrict__ qkv,
                                                   bf16* __restrict__ out_hi,
                                                   bf16* __restrict__ out_lo) {
    extern __shared__ float sm[];
    float* qs = sm;                   // [64][48]
    float* ks = qs + 64 * 48;
    float* vs = ks + 64 * 48;
    float* ws = vs + 64 * 48;         // [64][64]

    const int bh = blockIdx.x;
    const int b  = bh >> 3;
    const int h  = bh & 7;
    const int tid = threadIdx.x;
    const size_t base = (size_t)b * TT * QKVN + (size_t)h * HD;

    for (int idx = tid; idx < 64 * 12; idx += 128) {
        int t  = idx / 12;
        int c4 = (idx % 12) * 4;
        const float* p = qkv + base + (size_t)t * QKVN + c4;
        *(float4*)&qs[t * 48 + c4] = *(const float4*)p;
        *(float4*)&ks[t * 48 + c4] = *(const float4*)(p + C);
        *(float4*)&vs[t * 48 + c4] = *(const float4*)(p + 2 * C);
    }
    __syncthreads();

    const float scale = 2.449489742783178f;  // 48 * 384^-0.5

    for (int idx = tid; idx < 64 * 64; idx += 128) {
        int i = idx >> 6, j = idx & 63;
        if (j > i) continue;
        float sx = 0.f, sy = 0.f, sz = 0.f, sw = 0.f;
#pragma unroll
        for (int d4 = 0; d4 < 12; d4++) {
            float4 qv = *(const float4*)&qs[i * 48 + d4 * 4];
            float4 kv = *(const float4*)&ks[j * 48 + d4 * 4];
            sx += qv.x * kv.x; sy += qv.y * kv.y;
            sz += qv.z * kv.z; sw += qv.w * kv.w;
        }
        ws[i * 64 + j] = (sx + sy + sz + sw) * scale;
    }
    __syncthreads();

    if (tid < 64) {
        int i = tid;
        float m = -1e30f;
        for (int j = 0; j <= i; j++) m = fmaxf(m, ws[i * 64 + j]);
        float s = 0.f;
        for (int j = 0; j <= i; j++) {
            float e = expf(ws[i * 64 + j] - m);
            ws[i * 64 + j] = e;
            s += e;
        }
        float inv = 1.f / s;
        for (int j = 0; j <= i; j++) ws[i * 64 + j] *= inv;
    }
    __syncthreads();

    for (int idx = tid; idx < 64 * 12; idx += 128) {
        int i  = idx / 12;
        int d4 = (idx % 12) * 4;
        float ax = 0.f, ay = 0.f, az = 0.f, aw = 0.f;
        for (int j = 0; j <= i; j++) {
            float w = ws[i * 64 + j];
            float4 vv = *(const float4*)&vs[j * 48 + d4];
            ax += w * vv.x; ay += w * vv.y; az += w * vv.z; aw += w * vv.w;
        }
        size_t o = (size_t)(b * TT + i) * C + h * HD + d4;
        bf16 h0, l0, h1, l1, h2, l2, h3, l3;
        split_bf16(ax, h0, l0); split_bf16(ay, h1, l1);
        split_bf16(az, h2, l2); split_bf16(aw, h3, l3);
        __nv_bfloat162 hA; hA.x = h0; hA.y = h1;
        __nv_bfloat162 hB; hB.x = h2; hB.y = h3;
        __nv_bfloat162 lA; lA.x = l0; lA.y = l1;
        __nv_bfloat162 lB; lB.x = l2; lB.y = l3;
        *(__nv_bfloat162*)(out_hi + o)     = hA;
        *(__nv_bfloat162*)(out_hi + o + 2) = hB;
        *(__nv_bfloat162*)(out_lo + o)     = lA;
        *(__nv_bfloat162*)(out_lo + o + 2) = lB;
    }
}

// ---------------- launch ----------------
extern "C" void kernel_launch(void* const* d_in, const int* in_sizes, int n_in,
                              void* d_out, int out_size) {
    const float* x     = (const float*)d_in[0];
    const float* ln1_g = (const float*)d_in[1];
    const float* ln1_b = (const float*)d_in[2];
    const float* ln2_g = (const float*)d_in[3];
    const float* ln2_b = (const float*)d_in[4];
    const float* Wq    = (const float*)d_in[5];
    const float* Wk    = (const float*)d_in[6];
    const float* Wv    = (const float*)d_in[7];
    const float* Wp    = (const float*)d_in[8];
    const float* bp    = (const float*)d_in[9];
    const float* W1    = (const float*)d_in[10];
    const float* b1    = (const float*)d_in[11];
    const float* W2    = (const float*)d_in[12];
    const float* b2    = (const float*)d_in[13];
    float* out = (float*)d_out;

    bf16 *ph_hi, *ph_lo, *pattn_hi, *pattn_lo, *phid_hi, *phid_lo;
    bf16 *pwqkv_hi, *pwqkv_lo, *pwp_hi, *pwp_lo, *pw1_hi, *pw1_lo, *pw2_hi, *pw2_lo;
    float *pqkv, *px2;
    cudaGetSymbolAddress((void**)&ph_hi, g_h_hi);     cudaGetSymbolAddress((void**)&ph_lo, g_h_lo);
    cudaGetSymbolAddress((void**)&pqkv, g_qkv);
    cudaGetSymbolAddress((void**)&pattn_hi, g_attn_hi); cudaGetSymbolAddress((void**)&pattn_lo, g_attn_lo);
    cudaGetSymbolAddress((void**)&px2, g_x2);
    cudaGetSymbolAddress((void**)&phid_hi, g_hid_hi); cudaGetSymbolAddress((void**)&phid_lo, g_hid_lo);
    cudaGetSymbolAddress((void**)&pwqkv_hi, g_wqkv_hi); cudaGetSymbolAddress((void**)&pwqkv_lo, g_wqkv_lo);
    cudaGetSymbolAddress((void**)&pwp_hi, g_wp_hi);   cudaGetSymbolAddress((void**)&pwp_lo, g_wp_lo);
    cudaGetSymbolAddress((void**)&pw1_hi, g_w1_hi);   cudaGetSymbolAddress((void**)&pw1_lo, g_w1_lo);
    cudaGetSymbolAddress((void**)&pw2_hi, g_w2_hi);   cudaGetSymbolAddress((void**)&pw2_lo, g_w2_lo);

    static int attr_set = 0;
    const int attn_smem = (3 * 64 * 48 + 64 * 64) * (int)sizeof(float);
    if (!attr_set) {
        cudaFuncSetAttribute(attn_kernel, cudaFuncAttributeMaxDynamicSharedMemorySize, attn_smem);
        cudaFuncSetAttribute(mma_gemm<0>, cudaFuncAttributeMaxDynamicSharedMemorySize, GEMM_SMEM);
        cudaFuncSetAttribute(mma_gemm<1>, cudaFuncAttributeMaxDynamicSharedMemorySize, GEMM_SMEM);
        cudaFuncSetAttribute(mma_gemm<2>, cudaFuncAttributeMaxDynamicSharedMemorySize, GEMM_SMEM);
        attr_set = 1;
    }

    // weight prep (split + transpose to [N,K])
    prep_qkv_kernel<<<(QKVN * C + 255) / 256, 256>>>(Wq, Wk, Wv, pwqkv_hi, pwqkv_lo);
    prep_t_kernel<<<(C * C + 255) / 256, 256>>>(Wp, pwp_hi, pwp_lo, C, C);
    prep_t_kernel<<<(C * C4 + 255) / 256, 256>>>(W1, pw1_hi, pw1_lo, C, C4);
    prep_t_kernel<<<(C4 * C + 255) / 256, 256>>>(W2, pw2_hi, pw2_lo, C4, C);

    // LN1
    ln_kernel<<<BT / 8, dim3(32, 8)>>>(x, ln1_g, ln1_b, ph_hi, ph_lo);
    // QKV: [BT,384] x [1152,384]^T -> fp32
    mma_gemm<0><<<dim3(QKVN / 128, BT / 128), 256, GEMM_SMEM>>>(
        ph_hi, ph_lo, pwqkv_hi, pwqkv_lo, nullptr, nullptr, pqkv, nullptr, nullptr, QKVN, C);
    // attention
    attn_kernel<<<BATCH * NH, 128, attn_smem>>>(pqkv, pattn_hi, pattn_lo);
    // proj + bias + residual -> x2 (fp32)
    mma_gemm<1><<<dim3(C / 128, BT / 128), 256, GEMM_SMEM>>>(
        pattn_hi, pattn_lo, pwp_hi, pwp_lo, bp, x, px2, nullptr, nullptr, C, C);
    // LN2
    ln_kernel<<<BT / 8, dim3(32, 8)>>>(px2, ln2_g, ln2_b, ph_hi, ph_lo);
    // FFN1 + bias + relu -> hidden (split)
    mma_gemm<2><<<dim3(C4 / 128, BT / 128), 256, GEMM_SMEM>>>(
        ph_hi, ph_lo, pw1_hi, pw1_lo, b1, nullptr, nullptr, phid_hi, phid_lo, C4, C);
    // FFN2 + bias + residual -> out
    mma_gemm<1><<<dim3(C / 128, BT / 128), 256, GEMM_SMEM>>>(
        phid_hi, phid_lo, pw2_hi, pw2_lo, b2, px2, out, nullptr, nullptr, C, C4);
}